// round 1
// baseline (speedup 1.0000x reference)
#include <cuda_runtime.h>

// OnlineHadamard: out = had_rem @ (FHT64 blocks of x) * 1/sqrt(11008)
// x: [rows, 11008] fp32, viewed [rows, 172, 64]
//   step 1: y[k][n] = sum_m x[k][m] * H64[n][m] * scale   (Sylvester FHT over inner 64)
//   step 2: out[j][m] = sum_k had[j][k] * y[k][m]          (172x172 dense)
//
// Strategy (round 0 baseline):
//   - persistent-ish CTAs, grid-stride over rows, 1 CTA/SM (big smem)
//   - had transposed into smem once per CTA: had_s[k][j] (j padded to 192, zero fill)
//     -> A operand pairs load directly as packed 8B f32x2
//   - FHT64 in registers: lane holds (e[2l], e[2l+1]); stage0 in-thread, 5 shfl.bfly stages
//   - GEMM in packed fp32x2 (Blackwell fma.rn.f32x2): thread tile 6j x 4m = 12 FFMA2/k

#define KDIM 172
#define MDIM 64
#define NROW 11008
#define JPAD 192
#define NTHREADS 512
#define NWARPS (NTHREADS / 32)
#define HAD_S_FLOATS (KDIM * JPAD)                      // 33024
#define Y_S_FLOATS   (KDIM * MDIM)                      // 11008
#define SMEM_BYTES   ((HAD_S_FLOATS + Y_S_FLOATS) * 4)  // 176128

__device__ __forceinline__ unsigned long long pack2(float lo, float hi) {
    unsigned long long r;
    asm("mov.b64 %0, {%1, %2};" : "=l"(r) : "f"(lo), "f"(hi));
    return r;
}
__device__ __forceinline__ void fma2(unsigned long long &d,
                                     unsigned long long a,
                                     unsigned long long b) {
    asm("fma.rn.f32x2 %0, %1, %2, %0;" : "+l"(d) : "l"(a), "l"(b));
}
__device__ __forceinline__ float2 unpack2(unsigned long long v) {
    float2 f;
    asm("mov.b64 {%0, %1}, %2;" : "=f"(f.x), "=f"(f.y) : "l"(v));
    return f;
}

__global__ __launch_bounds__(NTHREADS, 1)
void onl_had_kernel(const float* __restrict__ x,
                    const float* __restrict__ had,
                    float* __restrict__ out,
                    int rows)
{
    extern __shared__ float smem[];
    float* had_s = smem;                   // [KDIM][JPAD]: had_s[k][j] = had[j][k]
    float* y_s   = smem + HAD_S_FLOATS;    // [KDIM][MDIM]

    const int tid  = threadIdx.x;
    const int lane = tid & 31;
    const int warp = tid >> 5;

    // One-time per CTA: load had transposed (k-major) with zero-padded j
    for (int idx = tid; idx < HAD_S_FLOATS; idx += NTHREADS) {
        int k = idx / JPAD;
        int j = idx - k * JPAD;
        had_s[idx] = (j < KDIM) ? had[j * KDIM + k] : 0.0f;
    }
    __syncthreads();

    const float scale = rsqrtf((float)NROW);

    const int tm = tid & 15;   // 0..15 -> m0 = tm*4
    const int tj = tid >> 4;   // 0..31 -> j0 = tj*6 (j padded to 192)
    const int m0 = tm * 4;
    const int j0 = tj * 6;

    for (int row = blockIdx.x; row < rows; row += gridDim.x) {
        const float* xr   = x   + (size_t)row * NROW;
        float*       outr = out + (size_t)row * NROW;

        // ---------- Phase A: coalesced load + register FHT64 + scale ----------
        for (int c = warp; c < KDIM; c += NWARPS) {
            float2 v = *(const float2*)(xr + c * MDIM + 2 * lane);
            // stage 0 (element distance 1, in-thread)
            float p0 = v.x + v.y;
            float p1 = v.x - v.y;
            // stages 1..5 (element distance 2..32 == lane distance 1..16)
            #pragma unroll
            for (int s = 0; s < 5; s++) {
                int msk = 1 << s;
                float q0 = __shfl_xor_sync(0xffffffffu, p0, msk);
                float q1 = __shfl_xor_sync(0xffffffffu, p1, msk);
                if (lane & msk) { p0 = q0 - p0; p1 = q1 - p1; }
                else            { p0 = p0 + q0; p1 = p1 + q1; }
            }
            *(float2*)(y_s + c * MDIM + 2 * lane) = make_float2(p0 * scale, p1 * scale);
        }
        __syncthreads();

        // ---------- Phase B: C[j][m] = sum_k had_s[k][j] * y_s[k][m] ----------
        unsigned long long acc[3][4];
        #pragma unroll
        for (int p = 0; p < 3; p++)
            #pragma unroll
            for (int q = 0; q < 4; q++)
                acc[p][q] = 0ull;

        #pragma unroll 4
        for (int k = 0; k < KDIM; k++) {
            const float* hk = had_s + k * JPAD + j0;
            unsigned long long a0 = *(const unsigned long long*)(hk);     // {j0,  j0+1}
            unsigned long long a1 = *(const unsigned long long*)(hk + 2); // {j0+2,j0+3}
            unsigned long long a2 = *(const unsigned long long*)(hk + 4); // {j0+4,j0+5}
            float4 b = *(const float4*)(y_s + k * MDIM + m0);
            unsigned long long b0 = pack2(b.x, b.x);
            unsigned long long b1 = pack2(b.y, b.y);
            unsigned long long b2 = pack2(b.z, b.z);
            unsigned long long b3 = pack2(b.w, b.w);
            fma2(acc[0][0], a0, b0); fma2(acc[0][1], a0, b1);
            fma2(acc[0][2], a0, b2); fma2(acc[0][3], a0, b3);
            fma2(acc[1][0], a1, b0); fma2(acc[1][1], a1, b1);
            fma2(acc[1][2], a1, b2); fma2(acc[1][3], a1, b3);
            fma2(acc[2][0], a2, b0); fma2(acc[2][1], a2, b1);
            fma2(acc[2][2], a2, b2); fma2(acc[2][3], a2, b3);
        }

        // ---------- Epilogue: repack to float4 rows, guarded stores ----------
        #pragma unroll
        for (int p = 0; p < 3; p++) {
            float2 c0 = unpack2(acc[p][0]);
            float2 c1 = unpack2(acc[p][1]);
            float2 c2 = unpack2(acc[p][2]);
            float2 c3 = unpack2(acc[p][3]);
            int ja = j0 + 2 * p;
            if (ja < KDIM) {
                *(float4*)(outr + ja * MDIM + m0) =
                    make_float4(c0.x, c1.x, c2.x, c3.x);
            }
            if (ja + 1 < KDIM) {
                *(float4*)(outr + (ja + 1) * MDIM + m0) =
                    make_float4(c0.y, c1.y, c2.y, c3.y);
            }
        }
        __syncthreads();  // protect y_s before next row's Phase A
    }
}

extern "C" void kernel_launch(void* const* d_in, const int* in_sizes, int n_in,
                              void* d_out, int out_size) {
    const float* x   = (const float*)d_in[0];
    const float* had = (const float*)d_in[1];
    float* out = (float*)d_out;

    int rows = in_sizes[0] / NROW;  // 8192 for the bench shape

    cudaFuncSetAttribute(onl_had_kernel,
                         cudaFuncAttributeMaxDynamicSharedMemorySize, SMEM_BYTES);

    int grid = rows < 1024 ? rows : 1024;
    onl_had_kernel<<<grid, NTHREADS, SMEM_BYTES>>>(x, had, out, rows);
}

// round 3
// speedup vs baseline: 1.7990x; 1.7990x over previous
#include <cuda_runtime.h>
#include <cuda_bf16.h>
#include <cstdint>

// OnlineHadamard via legacy tensor-core path (mma.sync bf16, valid on compute_103):
//   per row: y[k][m] = FHT64(x chunk k) * 1/sqrt(11008)     (shfl butterfly, fp32)
//            out[j][m] = sum_k had[j][k] * y[k][m]          (172x172, HMMA.16816)
// Split precision: v = vh + vl (bf16 each); 3 passes AhBh + AhBl + AlBh, fp32 accum.
// A (had) built once per CTA in smem; B (y) rebuilt per row.

#define KDIM 172
#define MDIM 64
#define NROW 11008
#define NT 512
#define NWARPS 16

#define ASTRB 368                 // A row stride bytes (184 halves), 16B aligned, conflict-free
#define BSTRB 144                 // B row stride bytes (72 halves),  16B aligned, conflict-free
#define A_BYTES (176 * ASTRB)     // 64768 per component
#define B_BYTES (176 * BSTRB)     // 25344 per component
#define OFF_AH 0
#define OFF_AL (A_BYTES)
#define OFF_BH (2 * A_BYTES)
#define OFF_BL (2 * A_BYTES + B_BYTES)
#define SMEM_DYN (2 * A_BYTES + 2 * B_BYTES)   // 180224

__device__ __forceinline__ uint32_t smem_u32(const void* p) {
    uint32_t a;
    asm("{ .reg .u64 t; cvta.to.shared.u64 t, %1; cvt.u32.u64 %0, t; }" : "=r"(a) : "l"(p));
    return a;
}
__device__ __forceinline__ void ldsm_x4(uint32_t& r0, uint32_t& r1, uint32_t& r2, uint32_t& r3,
                                        uint32_t addr) {
    asm volatile("ldmatrix.sync.aligned.m8n8.x4.shared.b16 {%0,%1,%2,%3}, [%4];"
                 : "=r"(r0), "=r"(r1), "=r"(r2), "=r"(r3) : "r"(addr));
}
__device__ __forceinline__ void ldsm_x2t(uint32_t& r0, uint32_t& r1, uint32_t addr) {
    asm volatile("ldmatrix.sync.aligned.m8n8.x2.trans.shared.b16 {%0,%1}, [%2];"
                 : "=r"(r0), "=r"(r1) : "r"(addr));
}
__device__ __forceinline__ void mma_bf16(float* c, uint32_t a0, uint32_t a1, uint32_t a2,
                                         uint32_t a3, uint32_t b0, uint32_t b1) {
    asm volatile("mma.sync.aligned.m16n8k16.row.col.f32.bf16.bf16.f32 "
                 "{%0,%1,%2,%3}, {%4,%5,%6,%7}, {%8,%9}, {%0,%1,%2,%3};"
                 : "+f"(c[0]), "+f"(c[1]), "+f"(c[2]), "+f"(c[3])
                 : "r"(a0), "r"(a1), "r"(a2), "r"(a3), "r"(b0), "r"(b1));
}

__global__ __launch_bounds__(NT, 1)
void onl_had_mma_kernel(const float* __restrict__ x,
                        const float* __restrict__ had,
                        float* __restrict__ out, int rows)
{
    extern __shared__ char sm[];
    const uint32_t sbase = smem_u32(sm);
    const int tid = threadIdx.x, lane = tid & 31, warp = tid >> 5;

    // ---- one-time: A = had as bf16 hi/lo, zero padded to 176x184 ----
    for (int idx = tid; idx < 176 * 184; idx += NT) {
        int j = idx / 184, k = idx - j * 184;
        float v = (j < KDIM && k < KDIM) ? had[j * KDIM + k] : 0.0f;
        __nv_bfloat16 h = __float2bfloat16(v);
        __nv_bfloat16 l = __float2bfloat16(v - __bfloat162float(h));
        *(__nv_bfloat16*)(sm + OFF_AH + j * ASTRB + 2 * k) = h;
        *(__nv_bfloat16*)(sm + OFF_AL + j * ASTRB + 2 * k) = l;
    }
    // ---- one-time: zero B pad rows k=172..175 (read by kt=10, never rewritten) ----
    for (int idx = tid; idx < 4 * 64; idx += NT) {
        int k = 172 + (idx >> 6), m = idx & 63;
        *(__nv_bfloat16*)(sm + OFF_BH + k * BSTRB + 2 * m) = __float2bfloat16(0.0f);
        *(__nv_bfloat16*)(sm + OFF_BL + k * BSTRB + 2 * m) = __float2bfloat16(0.0f);
    }
    __syncthreads();

    const float scale = rsqrtf((float)NROW);

    // ---- precomputed ldmatrix addresses ----
    // A x4 (non-trans, [j][k]): tiles (r0-7,k0-7),(r8-15,k0-7),(r0-7,k8-15),(r8-15,k8-15)
    const int jt = warp;                               // warps 0..10 do GEMM
    uint32_t a_row = (uint32_t)(jt * 16 + (lane & 7) + ((lane >> 3) & 1) * 8);
    uint32_t a_koff = (uint32_t)((lane >> 4) * 16);    // k-halves 0-7 vs 8-15
    uint32_t a_addr_h = sbase + OFF_AH + a_row * ASTRB + a_koff;
    uint32_t a_addr_l = sbase + OFF_AL + a_row * ASTRB + a_koff;
    // B x2 trans ([k][m]): threads 0-7 rows k0..k0+7, 8-15 rows k0+8..k0+15
    uint32_t b_row = (uint32_t)(lane & 15);
    uint32_t b_addr_h = sbase + OFF_BH + b_row * BSTRB;
    uint32_t b_addr_l = sbase + OFF_BL + b_row * BSTRB;

    // epilogue indices
    const int eq = lane & 3, er = lane >> 2;
    const int j1 = jt * 16 + er, j2 = j1 + 8;

    for (int row = blockIdx.x; row < rows; row += gridDim.x) {
        const float* xr = x + (size_t)row * NROW;

        // ---------- FHT phase (all 16 warps) ----------
        for (int c = warp; c < KDIM; c += NWARPS) {
            float2 v = *(const float2*)(xr + (c << 6) + 2 * lane);
            float p0 = v.x + v.y, p1 = v.x - v.y;
            #pragma unroll
            for (int s = 0; s < 5; s++) {
                int m = 1 << s;
                float q0 = __shfl_xor_sync(0xffffffffu, p0, m);
                float q1 = __shfl_xor_sync(0xffffffffu, p1, m);
                if (lane & m) { p0 = q0 - p0; p1 = q1 - p1; }
                else          { p0 = p0 + q0; p1 = p1 + q1; }
            }
            p0 *= scale; p1 *= scale;
            __nv_bfloat16 h0 = __float2bfloat16(p0), h1 = __float2bfloat16(p1);
            float r0 = p0 - __bfloat162float(h0), r1 = p1 - __bfloat162float(h1);
            __nv_bfloat162 hp = __halves2bfloat162(h0, h1);   // halves (m=2lane, 2lane+1)
            __nv_bfloat162 lp = __halves2bfloat162(__float2bfloat16(r0), __float2bfloat16(r1));
            *(uint32_t*)(sm + OFF_BH + c * BSTRB + lane * 4) = *(uint32_t*)&hp;
            *(uint32_t*)(sm + OFF_BL + c * BSTRB + lane * 4) = *(uint32_t*)&lp;
        }
        __syncthreads();

        // ---------- GEMM phase (warps 0..10) ----------
        if (warp < 11) {
            float acc[8][4];
            #pragma unroll
            for (int mt = 0; mt < 8; mt++) {
                acc[mt][0] = 0.f; acc[mt][1] = 0.f; acc[mt][2] = 0.f; acc[mt][3] = 0.f;
            }
            for (int kt = 0; kt < 11; kt++) {
                uint32_t ah0, ah1, ah2, ah3, al0, al1, al2, al3;
                ldsm_x4(ah0, ah1, ah2, ah3, a_addr_h + kt * 32);
                ldsm_x4(al0, al1, al2, al3, a_addr_l + kt * 32);
                uint32_t bko = (uint32_t)(kt * 16 * BSTRB);
                #pragma unroll
                for (int mt = 0; mt < 8; mt++) {
                    uint32_t bh0, bh1, bl0, bl1;
                    ldsm_x2t(bh0, bh1, b_addr_h + bko + mt * 16);
                    ldsm_x2t(bl0, bl1, b_addr_l + bko + mt * 16);
                    mma_bf16(acc[mt], ah0, ah1, ah2, ah3, bh0, bh1);
                    mma_bf16(acc[mt], ah0, ah1, ah2, ah3, bl0, bl1);
                    mma_bf16(acc[mt], al0, al1, al2, al3, bh0, bh1);
                }
            }
            // ---------- epilogue ----------
            float* orow = out + (size_t)row * NROW;
            if (j1 < KDIM) {
                float* o1 = orow + j1 * MDIM + eq * 2;
                #pragma unroll
                for (int mt = 0; mt < 8; mt++)
                    *(float2*)(o1 + mt * 8) = make_float2(acc[mt][0], acc[mt][1]);
            }
            if (j2 < KDIM) {
                float* o2 = orow + j2 * MDIM + eq * 2;
                #pragma unroll
                for (int mt = 0; mt < 8; mt++)
                    *(float2*)(o2 + mt * 8) = make_float2(acc[mt][2], acc[mt][3]);
            }
        }
        __syncthreads();   // protect B before next row's FHT
    }
}

extern "C" void kernel_launch(void* const* d_in, const int* in_sizes, int n_in,
                              void* d_out, int out_size) {
    const float* x   = (const float*)d_in[0];
    const float* had = (const float*)d_in[1];
    float* out = (float*)d_out;
    int rows = in_sizes[0] / NROW;

    cudaFuncSetAttribute(onl_had_mma_kernel,
                         cudaFuncAttributeMaxDynamicSharedMemorySize, SMEM_DYN);
    int grid = rows < 152 ? rows : 152;
    onl_had_mma_kernel<<<grid, NT, SMEM_DYN>>>(x, had, out, rows);
}